// round 3
// baseline (speedup 1.0000x reference)
#include <cuda_runtime.h>
#include <math.h>

#define N_IMG 32
#define ROWS_PER_IMG 262144              // 128*128*64 / 4 float4-rows per image
#define K1_CTAS_PER_IMG 64
#define K1_THREADS 256
#define ROWS_PER_CTA (ROWS_PER_IMG / K1_CTAS_PER_IMG)   // 4096
#define ROWS_PER_THREAD (ROWS_PER_CTA / K1_THREADS)     // 16

// Deterministic scratch (no device allocation allowed).
__device__ float g_part[N_IMG][K1_CTAS_PER_IMG][14];
__device__ float g_coef[N_IMG][8];   // w0..w3, b, pad

// ---------------------------------------------------------------------------
// K1: per-image raw moments. Every float4 of the image is one patches row.
// Accumulate s[4] (column sums) and q[10] (upper-tri cross products).
// ---------------------------------------------------------------------------
__global__ void __launch_bounds__(K1_THREADS) k1_reduce(const float4* __restrict__ in) {
    const int img = blockIdx.x >> 6;
    const int cta = blockIdx.x & 63;
    const float4* p = in + (size_t)img * ROWS_PER_IMG + cta * ROWS_PER_CTA + threadIdx.x;

    float s0 = 0.f, s1 = 0.f, s2 = 0.f, s3 = 0.f;
    float q00 = 0.f, q01 = 0.f, q02 = 0.f, q03 = 0.f;
    float q11 = 0.f, q12 = 0.f, q13 = 0.f;
    float q22 = 0.f, q23 = 0.f, q33 = 0.f;

#pragma unroll
    for (int k = 0; k < ROWS_PER_THREAD; k++) {
        float4 v = __ldg(p + k * K1_THREADS);
        s0 += v.x; s1 += v.y; s2 += v.z; s3 += v.w;
        q00 = fmaf(v.x, v.x, q00); q01 = fmaf(v.x, v.y, q01);
        q02 = fmaf(v.x, v.z, q02); q03 = fmaf(v.x, v.w, q03);
        q11 = fmaf(v.y, v.y, q11); q12 = fmaf(v.y, v.z, q12);
        q13 = fmaf(v.y, v.w, q13);
        q22 = fmaf(v.z, v.z, q22); q23 = fmaf(v.z, v.w, q23);
        q33 = fmaf(v.w, v.w, q33);
    }

    float vals[14] = {s0, s1, s2, s3, q00, q01, q02, q03, q11, q12, q13, q22, q23, q33};

    __shared__ float sm[8][14];
    const int lane = threadIdx.x & 31;
    const int warp = threadIdx.x >> 5;

#pragma unroll
    for (int i = 0; i < 14; i++) {
        float v = vals[i];
#pragma unroll
        for (int off = 16; off; off >>= 1)
            v += __shfl_down_sync(0xffffffffu, v, off);
        if (lane == 0) sm[warp][i] = v;
    }
    __syncthreads();
    if (warp == 0 && lane < 14) {
        float v = 0.f;
#pragma unroll
        for (int w = 0; w < 8; w++) v += sm[w][lane];
        g_part[img][cta][lane] = v;
    }
}

// ---------------------------------------------------------------------------
// K2: per-image final reduction (fp64), stats, 4x4 Jacobi eigensolve,
// emit affine coefficients w[4], b.
// ---------------------------------------------------------------------------
__global__ void k2_solve() {
    const int img = blockIdx.x;
    const int t = threadIdx.x;
    __shared__ double red[14];

    if (t < 14) {
        double acc = 0.0;
#pragma unroll 4
        for (int c = 0; c < K1_CTAS_PER_IMG; c++)
            acc += (double)g_part[img][c][t];
        red[t] = acc;
    }
    __syncthreads();

    if (t == 0) {
        const double N = (double)ROWS_PER_IMG;
        double S[4] = {red[0], red[1], red[2], red[3]};
        double Q[4][4];
        Q[0][0] = red[4];  Q[0][1] = red[5];  Q[0][2] = red[6];  Q[0][3] = red[7];
        Q[1][1] = red[8];  Q[1][2] = red[9];  Q[1][3] = red[10];
        Q[2][2] = red[11]; Q[2][3] = red[12]; Q[3][3] = red[13];
        Q[1][0] = Q[0][1]; Q[2][0] = Q[0][2]; Q[3][0] = Q[0][3];
        Q[2][1] = Q[1][2]; Q[3][1] = Q[1][3]; Q[3][2] = Q[2][3];

        double mu[4], inv[4];
#pragma unroll
        for (int i = 0; i < 4; i++) {
            mu[i] = S[i] / N;
            double var = Q[i][i] / N - mu[i] * mu[i];
            if (var < 0.0) var = 0.0;
            double sd = sqrt(var);
            inv[i] = (sd == 0.0) ? 0.0 : 1.0 / sd;
        }

        // Gram of normalized patches from raw moments.
        double A[4][4];
        for (int i = 0; i < 4; i++)
            for (int j = 0; j < 4; j++)
                A[i][j] = (Q[i][j] - N * mu[i] * mu[j]) * inv[i] * inv[j];

        // Cyclic Jacobi eigensolve (exact for 4x4; quadratic convergence).
        double V[4][4] = {{1,0,0,0},{0,1,0,0},{0,0,1,0},{0,0,0,1}};
        for (int sweep = 0; sweep < 20; sweep++) {
            double off = fabs(A[0][1]) + fabs(A[0][2]) + fabs(A[0][3])
                       + fabs(A[1][2]) + fabs(A[1][3]) + fabs(A[2][3]);
            if (off == 0.0) break;
            for (int p = 0; p < 3; p++) {
                for (int q = p + 1; q < 4; q++) {
                    double apq = A[p][q];
                    if (apq == 0.0) continue;
                    double theta = (A[q][q] - A[p][p]) / (2.0 * apq);
                    double tt = ((theta >= 0.0) ? 1.0 : -1.0)
                              / (fabs(theta) + sqrt(theta * theta + 1.0));
                    double c = 1.0 / sqrt(tt * tt + 1.0);
                    double s = tt * c;
                    // A <- R^T A R  (column update then row update)
                    for (int k = 0; k < 4; k++) {
                        double akp = A[k][p], akq = A[k][q];
                        A[k][p] = c * akp - s * akq;
                        A[k][q] = s * akp + c * akq;
                    }
                    for (int k = 0; k < 4; k++) {
                        double apk = A[p][k], aqk = A[q][k];
                        A[p][k] = c * apk - s * aqk;
                        A[q][k] = s * apk + c * aqk;
                    }
                    // V <- V R (columns are eigenvectors)
                    for (int k = 0; k < 4; k++) {
                        double vkp = V[k][p], vkq = V[k][q];
                        V[k][p] = c * vkp - s * vkq;
                        V[k][q] = s * vkp + c * vkq;
                    }
                }
            }
        }

        int best = 0;
        for (int i = 1; i < 4; i++)
            if (A[i][i] > A[best][best]) best = i;

        double v[4], sum = 0.0;
#pragma unroll
        for (int i = 0; i < 4; i++) { v[i] = V[i][best]; sum += v[i]; }
        double sgn = (sum < 0.0) ? -1.0 : 1.0;

        double b = 0.0;
#pragma unroll
        for (int i = 0; i < 4; i++) {
            double wi = sgn * v[i] * inv[i];
            g_coef[img][i] = (float)wi;
            b -= wi * mu[i];
        }
        g_coef[img][4] = (float)b;
    }
}

// ---------------------------------------------------------------------------
// K3: projection. out flat index o == patches row index; map to the memory
// float4 of that row (512B-contiguous per warp), apply affine, store.
// ---------------------------------------------------------------------------
__global__ void __launch_bounds__(256) k3_project(const float4* __restrict__ in,
                                                  float* __restrict__ out) {
    const int o = blockIdx.x * 256 + threadIdx.x;
    const int img = o >> 18;           // / 262144
    const int lo  = o & 262143;
    const int S     = lo >> 6;         // h2*64 + w2
    const int c_out = lo & 63;
    const int h2 = S >> 6, w2 = S & 63;
    const int pp = c_out >> 4;         // ph*2 + pw
    const int cg = c_out & 15;
    const int ph = pp >> 1, pw = pp & 1;
    const int m = (((h2 << 1) + ph) * 128 + ((w2 << 1) + pw)) * 16 + cg;

    float4 x = __ldg(in + (size_t)img * ROWS_PER_IMG + m);
    const float* cf = g_coef[img];
    float w0 = cf[0], w1 = cf[1], w2c = cf[2], w3 = cf[3], b = cf[4];
    out[o] = fmaf(w0, x.x, fmaf(w1, x.y, fmaf(w2c, x.z, fmaf(w3, x.w, b))));
}

extern "C" void kernel_launch(void* const* d_in, const int* in_sizes, int n_in,
                              void* d_out, int out_size) {
    const float4* in = (const float4*)d_in[0];
    float* out = (float*)d_out;
    k1_reduce<<<N_IMG * K1_CTAS_PER_IMG, K1_THREADS>>>(in);
    k2_solve<<<N_IMG, 64>>>();
    k3_project<<<(N_IMG * ROWS_PER_IMG) / 256, 256>>>(in, out);
}

// round 4
// speedup vs baseline: 5.9440x; 5.9440x over previous
#include <cuda_runtime.h>
#include <math.h>

#define N_IMG 32
#define ROWS_PER_IMG 262144              // 128*128*64 / 4 float4-rows per image
#define K1_CTAS_PER_IMG 64
#define K1_THREADS 256
#define ROWS_PER_CTA (ROWS_PER_IMG / K1_CTAS_PER_IMG)   // 4096
#define ROWS_PER_THREAD (ROWS_PER_CTA / K1_THREADS)     // 16

// Deterministic scratch (no device allocation allowed).
__device__ float g_part[N_IMG][K1_CTAS_PER_IMG][14];
__device__ float g_coef[N_IMG][8];   // w0..w3, b, pad

// ---------------------------------------------------------------------------
// K1: per-image raw moments. Every float4 of the image is one patches row.
// Accumulate s[4] (column sums) and q[10] (upper-tri cross products).
// ---------------------------------------------------------------------------
__global__ void __launch_bounds__(K1_THREADS) k1_reduce(const float4* __restrict__ in) {
    const int img = blockIdx.x >> 6;
    const int cta = blockIdx.x & 63;
    const float4* p = in + (size_t)img * ROWS_PER_IMG + cta * ROWS_PER_CTA + threadIdx.x;

    float s0 = 0.f, s1 = 0.f, s2 = 0.f, s3 = 0.f;
    float q00 = 0.f, q01 = 0.f, q02 = 0.f, q03 = 0.f;
    float q11 = 0.f, q12 = 0.f, q13 = 0.f;
    float q22 = 0.f, q23 = 0.f, q33 = 0.f;

#pragma unroll
    for (int k = 0; k < ROWS_PER_THREAD; k++) {
        float4 v = __ldg(p + k * K1_THREADS);
        s0 += v.x; s1 += v.y; s2 += v.z; s3 += v.w;
        q00 = fmaf(v.x, v.x, q00); q01 = fmaf(v.x, v.y, q01);
        q02 = fmaf(v.x, v.z, q02); q03 = fmaf(v.x, v.w, q03);
        q11 = fmaf(v.y, v.y, q11); q12 = fmaf(v.y, v.z, q12);
        q13 = fmaf(v.y, v.w, q13);
        q22 = fmaf(v.z, v.z, q22); q23 = fmaf(v.z, v.w, q23);
        q33 = fmaf(v.w, v.w, q33);
    }

    float vals[14] = {s0, s1, s2, s3, q00, q01, q02, q03, q11, q12, q13, q22, q23, q33};

    __shared__ float sm[8][14];
    const int lane = threadIdx.x & 31;
    const int warp = threadIdx.x >> 5;

#pragma unroll
    for (int i = 0; i < 14; i++) {
        float v = vals[i];
#pragma unroll
        for (int off = 16; off; off >>= 1)
            v += __shfl_down_sync(0xffffffffu, v, off);
        if (lane == 0) sm[warp][i] = v;
    }
    __syncthreads();
    if (warp == 0 && lane < 14) {
        float v = 0.f;
#pragma unroll
        for (int w = 0; w < 8; w++) v += sm[w][lane];
        g_part[img][cta][lane] = v;
    }
}

// ---------------------------------------------------------------------------
// K2: per-image final reduction (fp64, non-iterative part), stats, then
// SHIFTED gram E = Gram - N*I in fp64 (cancellation-safe), and the iterative
// Jacobi eigensolve in fp32 on E (E_ii == 0 exactly; |E_ij| ~ O(sqrt(N))).
// Eigenvectors of Gram == eigenvectors of E; top eigenvalue ordering matches
// (Gram = N*I + E). fp32 with a REAL convergence break: the fp64 version
// burned ~395us running 20 full sweeps of serial fp64 div/sqrt chains.
// ---------------------------------------------------------------------------
__global__ void k2_solve() {
    const int img = blockIdx.x;
    const int t = threadIdx.x;
    __shared__ double red[14];

    if (t < 14) {
        double acc = 0.0;
#pragma unroll 4
        for (int c = 0; c < K1_CTAS_PER_IMG; c++)
            acc += (double)g_part[img][c][t];
        red[t] = acc;
    }
    __syncthreads();

    if (t == 0) {
        const double N = (double)ROWS_PER_IMG;
        double S[4] = {red[0], red[1], red[2], red[3]};
        double Q[4][4];
        Q[0][0] = red[4];  Q[0][1] = red[5];  Q[0][2] = red[6];  Q[0][3] = red[7];
        Q[1][1] = red[8];  Q[1][2] = red[9];  Q[1][3] = red[10];
        Q[2][2] = red[11]; Q[2][3] = red[12]; Q[3][3] = red[13];
        Q[1][0] = Q[0][1]; Q[2][0] = Q[0][2]; Q[3][0] = Q[0][3];
        Q[2][1] = Q[1][2]; Q[3][1] = Q[1][3]; Q[3][2] = Q[2][3];

        double mu[4], inv[4];
        bool zerov[4];
#pragma unroll
        for (int i = 0; i < 4; i++) {
            mu[i] = S[i] / N;
            double var = Q[i][i] / N - mu[i] * mu[i];
            if (var < 0.0) var = 0.0;
            double sd = sqrt(var);
            zerov[i] = (sd == 0.0);
            inv[i] = zerov[i] ? 0.0 : 1.0 / sd;
        }

        // Shifted gram E = Gram - N*I, formed in fp64 then cast to fp32.
        // Diagonal of the normalized gram is exactly N for non-degenerate
        // columns (Q_ii - N*mu_i^2 = N*var_i, times inv_i^2 = N), so E_ii=0.
        // Degenerate (sd==0) columns: gram row/col is 0, so E_ii = -N there;
        // keep that (it just pushes that axis to the bottom of the spectrum,
        // matching eigh on the gram with a zero row/col... gram eigenvalue 0
        // vs others ~N, so the zero-column axis is never the top eigenvector
        // either way).
        float A[4][4];
        for (int i = 0; i < 4; i++)
            for (int j = 0; j < 4; j++) {
                double g = (Q[i][j] - N * mu[i] * mu[j]) * inv[i] * inv[j];
                if (i == j) g = zerov[i] ? -N : 0.0;
                A[i][j] = (float)g;
            }

        // Cyclic Jacobi in fp32 with convergence break.
        float V[4][4] = {{1,0,0,0},{0,1,0,0},{0,0,1,0},{0,0,0,1}};
        for (int sweep = 0; sweep < 8; sweep++) {
            float off = fabsf(A[0][1]) + fabsf(A[0][2]) + fabsf(A[0][3])
                      + fabsf(A[1][2]) + fabsf(A[1][3]) + fabsf(A[2][3]);
            if (off < 1e-3f) break;   // entries are O(500); this is ~noise floor
            for (int p = 0; p < 3; p++) {
                for (int q = p + 1; q < 4; q++) {
                    float apq = A[p][q];
                    if (fabsf(apq) == 0.0f) continue;
                    float theta = (A[q][q] - A[p][p]) / (2.0f * apq);
                    float tt = ((theta >= 0.0f) ? 1.0f : -1.0f)
                             / (fabsf(theta) + sqrtf(theta * theta + 1.0f));
                    float c = rsqrtf(tt * tt + 1.0f);
                    float s = tt * c;
                    for (int k = 0; k < 4; k++) {
                        float akp = A[k][p], akq = A[k][q];
                        A[k][p] = c * akp - s * akq;
                        A[k][q] = s * akp + c * akq;
                    }
                    for (int k = 0; k < 4; k++) {
                        float apk = A[p][k], aqk = A[q][k];
                        A[p][k] = c * apk - s * aqk;
                        A[q][k] = s * apk + c * aqk;
                    }
                    for (int k = 0; k < 4; k++) {
                        float vkp = V[k][p], vkq = V[k][q];
                        V[k][p] = c * vkp - s * vkq;
                        V[k][q] = s * vkp + c * vkq;
                    }
                }
            }
        }

        int best = 0;
        for (int i = 1; i < 4; i++)
            if (A[i][i] > A[best][best]) best = i;

        float v[4]; float sum = 0.0f;
#pragma unroll
        for (int i = 0; i < 4; i++) { v[i] = V[i][best]; sum += v[i]; }
        double sgn = (sum < 0.0f) ? -1.0 : 1.0;

        double b = 0.0;
#pragma unroll
        for (int i = 0; i < 4; i++) {
            double wi = sgn * (double)v[i] * inv[i];
            g_coef[img][i] = (float)wi;
            b -= wi * mu[i];
        }
        g_coef[img][4] = (float)b;
    }
}

// ---------------------------------------------------------------------------
// K3: projection. out flat index o == patches row index; map to the memory
// float4 of that row (512B-contiguous per warp), apply affine, store.
// ---------------------------------------------------------------------------
__global__ void __launch_bounds__(256) k3_project(const float4* __restrict__ in,
                                                  float* __restrict__ out) {
    const int o = blockIdx.x * 256 + threadIdx.x;
    const int img = o >> 18;           // / 262144
    const int lo  = o & 262143;
    const int S     = lo >> 6;         // h2*64 + w2
    const int c_out = lo & 63;
    const int h2 = S >> 6, w2 = S & 63;
    const int pp = c_out >> 4;         // ph*2 + pw
    const int cg = c_out & 15;
    const int ph = pp >> 1, pw = pp & 1;
    const int m = (((h2 << 1) + ph) * 128 + ((w2 << 1) + pw)) * 16 + cg;

    float4 x = __ldg(in + (size_t)img * ROWS_PER_IMG + m);
    const float* cf = g_coef[img];
    float w0 = cf[0], w1 = cf[1], w2c = cf[2], w3 = cf[3], b = cf[4];
    out[o] = fmaf(w0, x.x, fmaf(w1, x.y, fmaf(w2c, x.z, fmaf(w3, x.w, b))));
}

extern "C" void kernel_launch(void* const* d_in, const int* in_sizes, int n_in,
                              void* d_out, int out_size) {
    const float4* in = (const float4*)d_in[0];
    float* out = (float*)d_out;
    k1_reduce<<<N_IMG * K1_CTAS_PER_IMG, K1_THREADS>>>(in);
    k2_solve<<<N_IMG, 64>>>();
    k3_project<<<(N_IMG * ROWS_PER_IMG) / 256, 256>>>(in, out);
}

// round 6
// speedup vs baseline: 6.8890x; 1.1590x over previous
#include <cuda_runtime.h>
#include <math.h>

#define N_IMG 32
#define ROWS_PER_IMG 262144              // 128*128*64 / 4 float4-rows per image
#define K1_CTAS_PER_IMG 64
#define K1_THREADS 256
#define ROWS_PER_CTA (ROWS_PER_IMG / K1_CTAS_PER_IMG)   // 4096
#define ROWS_PER_THREAD (ROWS_PER_CTA / K1_THREADS)     // 16
#define K1_BATCH 8

// Deterministic scratch (no device allocation allowed).
__device__ float g_part[N_IMG][K1_CTAS_PER_IMG][14];
__device__ float g_coef[N_IMG][8];   // w0..w3, b, pad

// ---------------------------------------------------------------------------
// K1: per-image raw moments. Every float4 of the image is one patches row.
// Batch-8 loads before accumulating to keep 8 LDG.128 in flight (MLP=8);
// the previous load->fma interleave serialized to a short window (issue=26%,
// DRAM=65%).
// ---------------------------------------------------------------------------
__global__ void __launch_bounds__(K1_THREADS) k1_reduce(const float4* __restrict__ in) {
    const int img = blockIdx.x >> 6;
    const int cta = blockIdx.x & 63;
    const float4* p = in + (size_t)img * ROWS_PER_IMG + cta * ROWS_PER_CTA + threadIdx.x;

    float s0 = 0.f, s1 = 0.f, s2 = 0.f, s3 = 0.f;
    float q00 = 0.f, q01 = 0.f, q02 = 0.f, q03 = 0.f;
    float q11 = 0.f, q12 = 0.f, q13 = 0.f;
    float q22 = 0.f, q23 = 0.f, q33 = 0.f;

#pragma unroll
    for (int g = 0; g < ROWS_PER_THREAD / K1_BATCH; g++) {
        float4 buf[K1_BATCH];
#pragma unroll
        for (int j = 0; j < K1_BATCH; j++)
            buf[j] = __ldg(p + (g * K1_BATCH + j) * K1_THREADS);
#pragma unroll
        for (int j = 0; j < K1_BATCH; j++) {
            float4 v = buf[j];
            s0 += v.x; s1 += v.y; s2 += v.z; s3 += v.w;
            q00 = fmaf(v.x, v.x, q00); q01 = fmaf(v.x, v.y, q01);
            q02 = fmaf(v.x, v.z, q02); q03 = fmaf(v.x, v.w, q03);
            q11 = fmaf(v.y, v.y, q11); q12 = fmaf(v.y, v.z, q12);
            q13 = fmaf(v.y, v.w, q13);
            q22 = fmaf(v.z, v.z, q22); q23 = fmaf(v.z, v.w, q23);
            q33 = fmaf(v.w, v.w, q33);
        }
    }

    float vals[14] = {s0, s1, s2, s3, q00, q01, q02, q03, q11, q12, q13, q22, q23, q33};

    __shared__ float sm[8][14];
    const int lane = threadIdx.x & 31;
    const int warp = threadIdx.x >> 5;

#pragma unroll
    for (int i = 0; i < 14; i++) {
        float v = vals[i];
#pragma unroll
        for (int off = 16; off; off >>= 1)
            v += __shfl_down_sync(0xffffffffu, v, off);
        if (lane == 0) sm[warp][i] = v;
    }
    __syncthreads();
    if (warp == 0 && lane < 14) {
        float v = 0.f;
#pragma unroll
        for (int w = 0; w < 8; w++) v += sm[w][lane];
        g_part[img][cta][lane] = v;
    }
}

// ---------------------------------------------------------------------------
// K2: per-image final reduction (fp64, non-iterative), stats, then SHIFTED
// gram E = Gram - N*I in fp64 (cancellation-safe) and Jacobi in fp32 on E
// with a real convergence break.
// ---------------------------------------------------------------------------
__global__ void k2_solve() {
    const int img = blockIdx.x;
    const int t = threadIdx.x;
    __shared__ double red[14];

    if (t < 14) {
        double acc = 0.0;
#pragma unroll 4
        for (int c = 0; c < K1_CTAS_PER_IMG; c++)
            acc += (double)g_part[img][c][t];
        red[t] = acc;
    }
    __syncthreads();

    if (t == 0) {
        const double N = (double)ROWS_PER_IMG;
        double S[4] = {red[0], red[1], red[2], red[3]};
        double Q[4][4];
        Q[0][0] = red[4];  Q[0][1] = red[5];  Q[0][2] = red[6];  Q[0][3] = red[7];
        Q[1][1] = red[8];  Q[1][2] = red[9];  Q[1][3] = red[10];
        Q[2][2] = red[11]; Q[2][3] = red[12]; Q[3][3] = red[13];
        Q[1][0] = Q[0][1]; Q[2][0] = Q[0][2]; Q[3][0] = Q[0][3];
        Q[2][1] = Q[1][2]; Q[3][1] = Q[1][3]; Q[3][2] = Q[2][3];

        double mu[4], inv[4];
        bool zerov[4];
#pragma unroll
        for (int i = 0; i < 4; i++) {
            mu[i] = S[i] / N;
            double var = Q[i][i] / N - mu[i] * mu[i];
            if (var < 0.0) var = 0.0;
            double sd = sqrt(var);
            zerov[i] = (sd == 0.0);
            inv[i] = zerov[i] ? 0.0 : 1.0 / sd;
        }

        float A[4][4];
        for (int i = 0; i < 4; i++)
            for (int j = 0; j < 4; j++) {
                double g = (Q[i][j] - N * mu[i] * mu[j]) * inv[i] * inv[j];
                if (i == j) g = zerov[i] ? -N : 0.0;
                A[i][j] = (float)g;
            }

        float V[4][4] = {{1,0,0,0},{0,1,0,0},{0,0,1,0},{0,0,0,1}};
        for (int sweep = 0; sweep < 8; sweep++) {
            float off = fabsf(A[0][1]) + fabsf(A[0][2]) + fabsf(A[0][3])
                      + fabsf(A[1][2]) + fabsf(A[1][3]) + fabsf(A[2][3]);
            if (off < 1e-3f) break;   // entries O(500); this is the fp32 noise floor
            for (int p = 0; p < 3; p++) {
                for (int q = p + 1; q < 4; q++) {
                    float apq = A[p][q];
                    if (fabsf(apq) == 0.0f) continue;
                    float theta = (A[q][q] - A[p][p]) / (2.0f * apq);
                    float tt = ((theta >= 0.0f) ? 1.0f : -1.0f)
                             / (fabsf(theta) + sqrtf(theta * theta + 1.0f));
                    float c = rsqrtf(tt * tt + 1.0f);
                    float s = tt * c;
                    for (int k = 0; k < 4; k++) {
                        float akp = A[k][p], akq = A[k][q];
                        A[k][p] = c * akp - s * akq;
                        A[k][q] = s * akp + c * akq;
                    }
                    for (int k = 0; k < 4; k++) {
                        float apk = A[p][k], aqk = A[q][k];
                        A[p][k] = c * apk - s * aqk;
                        A[q][k] = s * apk + c * aqk;
                    }
                    for (int k = 0; k < 4; k++) {
                        float vkp = V[k][p], vkq = V[k][q];
                        V[k][p] = c * vkp - s * vkq;
                        V[k][q] = s * vkp + c * vkq;
                    }
                }
            }
        }

        int best = 0;
        for (int i = 1; i < 4; i++)
            if (A[i][i] > A[best][best]) best = i;

        float v[4]; float sum = 0.0f;
#pragma unroll
        for (int i = 0; i < 4; i++) { v[i] = V[i][best]; sum += v[i]; }
        double sgn = (sum < 0.0f) ? -1.0 : 1.0;

        double b = 0.0;
#pragma unroll
        for (int i = 0; i < 4; i++) {
            double wi = sgn * (double)v[i] * inv[i];
            g_coef[img][i] = (float)wi;
            b -= wi * mu[i];
        }
        g_coef[img][4] = (float)b;
    }
}

// ---------------------------------------------------------------------------
// K3: projection, traversed in REVERSE block order. K1 just streamed the
// 128 MiB input through the ~126 MB L2: at K1's end everything except the
// oldest (first-loaded) few MiB is resident. Reading MRU-first turns nearly
// all K3 reads into L2 hits instead of chasing LRU evictions. Output stores
// use the streaming hint (__stcs) so the 32 MiB write stream doesn't evict
// the input we're about to read. (Across graph replays this also leaves
// image 0 MRU for the next replay's forward-order K1.)
// ---------------------------------------------------------------------------
__global__ void __launch_bounds__(256) k3_project(const float4* __restrict__ in,
                                                  float* __restrict__ out) {
    const int blk = gridDim.x - 1 - blockIdx.x;          // reverse traversal
    const int o = blk * 256 + threadIdx.x;
    const int img = o >> 18;           // / 262144
    const int lo  = o & 262143;
    const int S     = lo >> 6;         // h2*64 + w2
    const int c_out = lo & 63;
    const int h2 = S >> 6, w2 = S & 63;
    const int pp = c_out >> 4;         // ph*2 + pw
    const int cg = c_out & 15;
    const int ph = pp >> 1, pw = pp & 1;
    const int m = (((h2 << 1) + ph) * 128 + ((w2 << 1) + pw)) * 16 + cg;

    float4 x = __ldg(in + (size_t)img * ROWS_PER_IMG + m);
    const float* cf = g_coef[img];
    float w0 = cf[0], w1 = cf[1], w2c = cf[2], w3 = cf[3], b = cf[4];
    __stcs(out + o, fmaf(w0, x.x, fmaf(w1, x.y, fmaf(w2c, x.z, fmaf(w3, x.w, b)))));
}

extern "C" void kernel_launch(void* const* d_in, const int* in_sizes, int n_in,
                              void* d_out, int out_size) {
    const float4* in = (const float4*)d_in[0];
    float* out = (float*)d_out;
    k1_reduce<<<N_IMG * K1_CTAS_PER_IMG, K1_THREADS>>>(in);
    k2_solve<<<N_IMG, 64>>>();
    k3_project<<<(N_IMG * ROWS_PER_IMG) / 256, 256>>>(in, out);
}